// round 1
// baseline (speedup 1.0000x reference)
#include <cuda_runtime.h>
#include <math.h>

// Problem constants (match reference)
#define Bn 8
#define Nn 1000
#define Cn 81
#define Kn 100
#define Mn 28
#define MM (Mn*Mn)
#define IMG_W 1216.0f
#define IMG_H 800.0f
#define SCORE_THRESH 0.05f
#define NMS_THRESH 0.5f
// log(1000/16)
#define BBOX_CLIP 4.135166556742356f
#define CAP 20000

// Output layout: concat of [B,K,4] boxes, [B,K] scores, [B,K] labels, [B,K,1,M,M] masks (all f32)
#define OFF_B 0
#define OFF_S (Bn*Kn*4)
#define OFF_L (OFF_S + Bn*Kn)
#define OFF_M (OFF_L + Bn*Kn)

// ---------------- scratch (device globals; no allocation) ----------------
__device__ float g_scores[Bn*Cn*Nn];          // [b][c][n]
__device__ float g_boxes[Bn*Cn*Nn*4];         // [b][c][n][4] decoded+clipped
__device__ int   g_cand_count[Bn];
__device__ float g_cand_score[Bn*CAP];
__device__ int   g_cand_flat[Bn*CAP];
__device__ float4 g_cand_box[Bn*CAP];
__device__ unsigned long long g_key[Bn*CAP];
__device__ int   g_labels[Bn*Kn];

// ---------------- kernel 0: reset counters ----------------
__global__ void k_init() {
    int t = threadIdx.x;
    if (t < Bn) g_cand_count[t] = 0;
}

// ---------------- kernel 1: softmax + box decode/clip ----------------
// grid = B*N rows, block = 128 (thread c handles class c)
__global__ void k_softmax_decode(const float* __restrict__ logits,
                                 const float* __restrict__ reg,
                                 const float* __restrict__ props) {
    int row = blockIdx.x;            // b*N + n
    int c = threadIdx.x;
    __shared__ float red[128];

    float v = (c < Cn) ? logits[row*Cn + c] : -INFINITY;
    red[c] = v; __syncthreads();
    for (int s = 64; s > 0; s >>= 1) {
        if (c < s) red[c] = fmaxf(red[c], red[c+s]);
        __syncthreads();
    }
    float mx = red[0]; __syncthreads();
    float e = (c < Cn) ? expf(v - mx) : 0.0f;
    red[c] = e; __syncthreads();
    for (int s = 64; s > 0; s >>= 1) {
        if (c < s) red[c] += red[c+s];
        __syncthreads();
    }
    float sum = red[0];

    if (c < Cn) {
        int b = row / Nn;
        int n = row % Nn;
        float score = e / sum;
        g_scores[(b*Cn + c)*Nn + n] = score;

        float px1 = props[row*4+0], py1 = props[row*4+1];
        float px2 = props[row*4+2], py2 = props[row*4+3];
        float w = px2 - px1, h = py2 - py1;
        float cx = px1 + 0.5f*w, cy = py1 + 0.5f*h;

        const float* r = reg + (size_t)row*Cn*4 + c*4;
        float dx = r[0] / 10.0f;
        float dy = r[1] / 10.0f;
        float dw = fminf(r[2] / 5.0f, BBOX_CLIP);
        float dh = fminf(r[3] / 5.0f, BBOX_CLIP);
        float pcx = dx*w + cx;
        float pcy = dy*h + cy;
        float pw = expf(dw)*w;
        float ph = expf(dh)*h;
        float x1 = pcx - 0.5f*pw, y1 = pcy - 0.5f*ph;
        float x2 = pcx + 0.5f*pw, y2 = pcy + 0.5f*ph;
        x1 = fminf(fmaxf(x1, 0.0f), IMG_W);
        y1 = fminf(fmaxf(y1, 0.0f), IMG_H);
        x2 = fminf(fmaxf(x2, 0.0f), IMG_W);
        y2 = fminf(fmaxf(y2, 0.0f), IMG_H);
        float* bo = g_boxes + ((size_t)(b*Cn + c)*Nn + n)*4;
        bo[0] = x1; bo[1] = y1; bo[2] = x2; bo[3] = y2;
    }
}

// ---------------- kernel 2: per (b,class) sort + greedy NMS + candidate append --
// grid = B*(C-1), block = 256
__global__ void k_nms() {
    int pair = blockIdx.x;
    int b  = pair / (Cn-1);
    int cr = pair % (Cn-1);     // class index within [0,79]; real class = cr+1
    int cc = cr + 1;
    int tid = threadIdx.x;

    __shared__ unsigned long long key[1024];
    __shared__ float4 box[Nn];
    __shared__ float  area[Nn];
    __shared__ unsigned char keep[Nn];
    __shared__ int mS;

    const float* sc = g_scores + (size_t)(b*Cn + cc)*Nn;

    // pack keys: score bits (positive floats -> monotonic unsigned), tiebreak: smaller orig idx wins
    for (int i = tid; i < 1024; i += blockDim.x) {
        if (i < Nn) {
            float s = sc[i];
            key[i] = ((unsigned long long)__float_as_uint(s) << 32)
                   | (unsigned long long)(0xFFFFFFFFu - (unsigned)i);
        } else key[i] = 0ULL;
    }
    __syncthreads();

    // bitonic sort DESCENDING over 1024 keys
    for (int k = 2; k <= 1024; k <<= 1) {
        for (int j = k >> 1; j > 0; j >>= 1) {
            for (int i = tid; i < 1024; i += blockDim.x) {
                int ixj = i ^ j;
                if (ixj > i) {
                    unsigned long long a = key[i], bb = key[ixj];
                    bool up = ((i & k) == 0);
                    if (up ? (a < bb) : (a > bb)) { key[i] = bb; key[ixj] = a; }
                }
            }
            __syncthreads();
        }
    }

    // m = count of sorted scores > SCORE_THRESH (prefix length)
    if (tid == 0) mS = 0;
    __syncthreads();
    for (int i = tid; i < Nn; i += blockDim.x) {
        float s = __uint_as_float((unsigned)(key[i] >> 32));
        if (s > SCORE_THRESH) atomicMax(&mS, i + 1);
    }
    __syncthreads();
    int m = mS;

    // gather boxes for active prefix
    for (int i = tid; i < m; i += blockDim.x) {
        unsigned orig = 0xFFFFFFFFu - (unsigned)(key[i] & 0xFFFFFFFFull);
        const float* bp = g_boxes + ((size_t)(b*Cn + cc)*Nn + orig)*4;
        float4 bv; bv.x = bp[0]; bv.y = bp[1]; bv.z = bp[2]; bv.w = bp[3];
        box[i] = bv;
        area[i] = (bv.z - bv.x) * (bv.w - bv.y);
        keep[i] = 1;
    }
    __syncthreads();

    // sequential greedy suppression over the active prefix
    for (int i = 0; i < m; ++i) {
        __syncthreads();
        if (!keep[i]) continue;          // uniform: shared value after barrier
        float4 bi = box[i];
        float ai = area[i];
        for (int j = i + 1 + tid; j < m; j += blockDim.x) {
            float4 bj = box[j];
            float lx = fmaxf(bi.x, bj.x);
            float ly = fmaxf(bi.y, bj.y);
            float rx = fminf(bi.z, bj.z);
            float ry = fminf(bi.w, bj.w);
            float iw = fmaxf(rx - lx, 0.0f);
            float ih = fmaxf(ry - ly, 0.0f);
            float inter = iw * ih;
            float iou = inter / (ai + area[j] - inter + 1e-9f);
            if (iou > NMS_THRESH) keep[j] = 0;
        }
    }
    __syncthreads();

    // append survivors to the per-image candidate list
    for (int i = tid; i < m; i += blockDim.x) {
        if (keep[i]) {
            int pos = atomicAdd(&g_cand_count[b], 1);
            if (pos < CAP) {
                int o = b*CAP + pos;
                g_cand_score[o] = __uint_as_float((unsigned)(key[i] >> 32));
                g_cand_flat[o]  = cr*Nn + i;    // flat index into [C-1, N] sorted layout
                g_cand_box[o]   = box[i];
            }
        }
    }
}

// ---------------- kernel 3: per-image top-K selection ----------------
// grid = B, block = 256
__global__ void k_topk(float* __restrict__ out) {
    int b = blockIdx.x;
    int tid = threadIdx.x;
    int V = g_cand_count[b];
    if (V > CAP) V = CAP;

    // build destructible keys (score desc, then lower flat index first)
    for (int j = tid; j < V; j += blockDim.x) {
        int o = b*CAP + j;
        g_key[o] = ((unsigned long long)__float_as_uint(g_cand_score[o]) << 32)
                 | (unsigned long long)(0xFFFFFFFFu - (unsigned)g_cand_flat[o]);
    }
    __syncthreads();

    __shared__ unsigned long long sk[256];
    __shared__ int si[256];

    for (int k = 0; k < Kn; ++k) {
        unsigned long long bk = 0ULL; int bj = -1;
        for (int j = tid; j < V; j += blockDim.x) {
            unsigned long long v = g_key[b*CAP + j];
            if (v > bk) { bk = v; bj = j; }
        }
        sk[tid] = bk; si[tid] = bj;
        __syncthreads();
        for (int s = 128; s > 0; s >>= 1) {
            if (tid < s && sk[tid+s] > sk[tid]) { sk[tid] = sk[tid+s]; si[tid] = si[tid+s]; }
            __syncthreads();
        }
        if (tid == 0) {
            int d = b*Kn + k;
            if (sk[0] > 0ULL) {
                int o = b*CAP + si[0];
                float s  = g_cand_score[o];
                int flat = g_cand_flat[o];
                int lab  = flat / Nn + 1;
                float4 bx = g_cand_box[o];
                out[OFF_B + d*4 + 0] = bx.x;
                out[OFF_B + d*4 + 1] = bx.y;
                out[OFF_B + d*4 + 2] = bx.z;
                out[OFF_B + d*4 + 3] = bx.w;
                out[OFF_S + d] = s;
                out[OFF_L + d] = (float)lab;
                g_labels[d] = lab;
                g_key[o] = 0ULL;
            } else {
                out[OFF_B + d*4 + 0] = 0.0f;
                out[OFF_B + d*4 + 1] = 0.0f;
                out[OFF_B + d*4 + 2] = 0.0f;
                out[OFF_B + d*4 + 3] = 0.0f;
                out[OFF_S + d] = 0.0f;
                out[OFF_L + d] = 0.0f;
                g_labels[d] = 0;
            }
        }
        __syncthreads();
    }
}

// ---------------- kernel 4: mask gather + sigmoid ----------------
// grid = B*K, block = 256
__global__ void k_mask(const float* __restrict__ ml, float* __restrict__ out) {
    int d = blockIdx.x;                // b*K + k
    int lab = g_labels[d];
    const float* src = ml + ((size_t)d*Cn + lab)*MM;
    float* dst = out + OFF_M + (size_t)d*MM;
    for (int t = threadIdx.x; t < MM; t += blockDim.x) {
        float x = src[t];
        float p = (x >= 0.0f) ? 1.0f/(1.0f + expf(-x))
                              : expf(x)/(1.0f + expf(x));
        dst[t] = p;
    }
}

extern "C" void kernel_launch(void* const* d_in, const int* in_sizes, int n_in,
                              void* d_out, int out_size) {
    const float* logits = (const float*)d_in[0];   // [B*N, C]
    const float* reg    = (const float*)d_in[1];   // [B*N, C*4]
    const float* props  = (const float*)d_in[2];   // [B, N, 4]
    const float* ml     = (const float*)d_in[3];   // [B, K, C, M, M]
    float* out = (float*)d_out;

    k_init<<<1, 32>>>();
    k_softmax_decode<<<Bn*Nn, 128>>>(logits, reg, props);
    k_nms<<<Bn*(Cn-1), 256>>>();
    k_topk<<<Bn, 256>>>(out);
    k_mask<<<Bn*Kn, 256>>>(ml, out);
}

// round 2
// speedup vs baseline: 1.5545x; 1.5545x over previous
#include <cuda_runtime.h>
#include <math.h>

// Problem constants (match reference)
#define Bn 8
#define Nn 1000
#define Cn 81
#define Kn 100
#define Mn 28
#define MM (Mn*Mn)
#define IMG_W 1216.0f
#define IMG_H 800.0f
#define SCORE_THRESH 0.05f
#define NMS_THRESH 0.5f
// log(1000/16)
#define BBOX_CLIP 4.135166556742356f
#define CAP 20000
#define SORT_N 4096

// Output layout: concat of [B,K,4] boxes, [B,K] scores, [B,K] labels, [B,K,1,M,M] masks (all f32)
#define OFF_B 0
#define OFF_S (Bn*Kn*4)
#define OFF_L (OFF_S + Bn*Kn)
#define OFF_M (OFF_L + Bn*Kn)

// ---------------- scratch (device globals; no allocation) ----------------
__device__ float g_scores[Bn*Cn*Nn];          // [b][c][n]
__device__ float g_boxes[Bn*Cn*Nn*4];         // [b][c][n][4] decoded+clipped
__device__ int   g_cand_count[Bn];
__device__ float g_cand_score[Bn*CAP];
__device__ int   g_cand_flat[Bn*CAP];
__device__ float4 g_cand_box[Bn*CAP];
__device__ unsigned long long g_key[Bn*CAP];  // fallback path only
__device__ int   g_labels[Bn*Kn];

// ---------------- kernel 0: reset counters ----------------
__global__ void k_init() {
    int t = threadIdx.x;
    if (t < Bn) g_cand_count[t] = 0;
}

// ---------------- kernel 1: softmax + box decode/clip ----------------
// grid = B*N rows, block = 128 (thread c handles class c); warp-shuffle reductions
__global__ void k_softmax_decode(const float* __restrict__ logits,
                                 const float* __restrict__ reg,
                                 const float* __restrict__ props) {
    int row = blockIdx.x;            // b*N + n
    int c = threadIdx.x;
    int lane = c & 31;
    int wid = c >> 5;
    __shared__ float redm[4];
    __shared__ float reds[4];

    float v = (c < Cn) ? logits[row*Cn + c] : -INFINITY;
    float wm = v;
    #pragma unroll
    for (int off = 16; off > 0; off >>= 1)
        wm = fmaxf(wm, __shfl_xor_sync(0xFFFFFFFFu, wm, off));
    if (lane == 0) redm[wid] = wm;
    __syncthreads();
    float mx = fmaxf(fmaxf(redm[0], redm[1]), fmaxf(redm[2], redm[3]));

    float e = (c < Cn) ? expf(v - mx) : 0.0f;
    float ws = e;
    #pragma unroll
    for (int off = 16; off > 0; off >>= 1)
        ws += __shfl_xor_sync(0xFFFFFFFFu, ws, off);
    if (lane == 0) reds[wid] = ws;
    __syncthreads();
    float sum = reds[0] + reds[1] + reds[2] + reds[3];

    if (c < Cn) {
        int b = row / Nn;
        int n = row % Nn;
        float score = e / sum;
        g_scores[(b*Cn + c)*Nn + n] = score;

        float px1 = props[row*4+0], py1 = props[row*4+1];
        float px2 = props[row*4+2], py2 = props[row*4+3];
        float w = px2 - px1, h = py2 - py1;
        float cx = px1 + 0.5f*w, cy = py1 + 0.5f*h;

        const float* r = reg + (size_t)row*Cn*4 + c*4;
        float dx = r[0] / 10.0f;
        float dy = r[1] / 10.0f;
        float dw = fminf(r[2] / 5.0f, BBOX_CLIP);
        float dh = fminf(r[3] / 5.0f, BBOX_CLIP);
        float pcx = dx*w + cx;
        float pcy = dy*h + cy;
        float pw = expf(dw)*w;
        float ph = expf(dh)*h;
        float x1 = pcx - 0.5f*pw, y1 = pcy - 0.5f*ph;
        float x2 = pcx + 0.5f*pw, y2 = pcy + 0.5f*ph;
        x1 = fminf(fmaxf(x1, 0.0f), IMG_W);
        y1 = fminf(fmaxf(y1, 0.0f), IMG_H);
        x2 = fminf(fmaxf(x2, 0.0f), IMG_W);
        y2 = fminf(fmaxf(y2, 0.0f), IMG_H);
        float* bo = g_boxes + ((size_t)(b*Cn + c)*Nn + n)*4;
        bo[0] = x1; bo[1] = y1; bo[2] = x2; bo[3] = y2;
    }
}

// ---------------- kernel 2: per (b,class) sort + greedy NMS + candidate append --
// grid = B*(C-1), block = 256
__global__ void k_nms() {
    int pair = blockIdx.x;
    int b  = pair / (Cn-1);
    int cr = pair % (Cn-1);     // class index within [0,79]; real class = cr+1
    int cc = cr + 1;
    int tid = threadIdx.x;

    __shared__ unsigned long long key[1024];
    __shared__ float4 box[Nn];
    __shared__ float  area[Nn];
    __shared__ unsigned char keep[Nn];
    __shared__ int mS;

    const float* sc = g_scores + (size_t)(b*Cn + cc)*Nn;

    // pack keys: score bits (positive floats -> monotonic unsigned), tiebreak: smaller orig idx wins
    for (int i = tid; i < 1024; i += blockDim.x) {
        if (i < Nn) {
            float s = sc[i];
            key[i] = ((unsigned long long)__float_as_uint(s) << 32)
                   | (unsigned long long)(0xFFFFFFFFu - (unsigned)i);
        } else key[i] = 0ULL;
    }
    __syncthreads();

    // bitonic sort DESCENDING over 1024 keys
    for (int k = 2; k <= 1024; k <<= 1) {
        for (int j = k >> 1; j > 0; j >>= 1) {
            for (int i = tid; i < 1024; i += blockDim.x) {
                int ixj = i ^ j;
                if (ixj > i) {
                    unsigned long long a = key[i], bb = key[ixj];
                    bool up = ((i & k) == 0);
                    if (up ? (a < bb) : (a > bb)) { key[i] = bb; key[ixj] = a; }
                }
            }
            __syncthreads();
        }
    }

    // m = count of sorted scores > SCORE_THRESH (prefix length)
    if (tid == 0) mS = 0;
    __syncthreads();
    for (int i = tid; i < Nn; i += blockDim.x) {
        float s = __uint_as_float((unsigned)(key[i] >> 32));
        if (s > SCORE_THRESH) atomicMax(&mS, i + 1);
    }
    __syncthreads();
    int m = mS;

    // gather boxes for active prefix
    for (int i = tid; i < m; i += blockDim.x) {
        unsigned orig = 0xFFFFFFFFu - (unsigned)(key[i] & 0xFFFFFFFFull);
        const float* bp = g_boxes + ((size_t)(b*Cn + cc)*Nn + orig)*4;
        float4 bv; bv.x = bp[0]; bv.y = bp[1]; bv.z = bp[2]; bv.w = bp[3];
        box[i] = bv;
        area[i] = (bv.z - bv.x) * (bv.w - bv.y);
        keep[i] = 1;
    }
    __syncthreads();

    // sequential greedy suppression over the active prefix
    for (int i = 0; i < m; ++i) {
        __syncthreads();
        if (!keep[i]) continue;          // uniform: shared value after barrier
        float4 bi = box[i];
        float ai = area[i];
        for (int j = i + 1 + tid; j < m; j += blockDim.x) {
            float4 bj = box[j];
            float lx = fmaxf(bi.x, bj.x);
            float ly = fmaxf(bi.y, bj.y);
            float rx = fminf(bi.z, bj.z);
            float ry = fminf(bi.w, bj.w);
            float iw = fmaxf(rx - lx, 0.0f);
            float ih = fmaxf(ry - ly, 0.0f);
            float inter = iw * ih;
            float iou = inter / (ai + area[j] - inter + 1e-9f);
            if (iou > NMS_THRESH) keep[j] = 0;
        }
    }
    __syncthreads();

    // append survivors to the per-image candidate list
    for (int i = tid; i < m; i += blockDim.x) {
        if (keep[i]) {
            int pos = atomicAdd(&g_cand_count[b], 1);
            if (pos < CAP) {
                int o = b*CAP + pos;
                g_cand_score[o] = __uint_as_float((unsigned)(key[i] >> 32));
                g_cand_flat[o]  = cr*Nn + i;    // flat index into [C-1, N] sorted layout
                g_cand_box[o]   = box[i];
            }
        }
    }
}

// ---------------- kernel 3: per-image top-K via shared-memory bitonic sort ----
// grid = B, block = 512
// key u64: [63:32]=score bits, [31:15]=(0x1FFFF - flat), [14:0]=slot
// flat < 80000 < 2^17 and is unique per candidate, so (score desc, flat asc)
// ordering exactly reproduces lax.top_k tie-breaking; slot never decides.
__global__ void k_topk(float* __restrict__ out) {
    int b = blockIdx.x;
    int tid = threadIdx.x;
    int V = g_cand_count[b];
    if (V > CAP) V = CAP;

    __shared__ unsigned long long key[SORT_N];

    if (V <= SORT_N) {
        // load + pad
        for (int i = tid; i < SORT_N; i += blockDim.x) {
            if (i < V) {
                int o = b*CAP + i;
                unsigned flat = (unsigned)g_cand_flat[o];
                key[i] = ((unsigned long long)__float_as_uint(g_cand_score[o]) << 32)
                       | ((unsigned long long)(0x1FFFFu - flat) << 15)
                       | (unsigned long long)i;
            } else key[i] = 0ULL;
        }
        __syncthreads();

        // bitonic sort DESCENDING
        for (int k = 2; k <= SORT_N; k <<= 1) {
            for (int j = k >> 1; j > 0; j >>= 1) {
                for (int i = tid; i < SORT_N; i += blockDim.x) {
                    int ixj = i ^ j;
                    if (ixj > i) {
                        unsigned long long a = key[i], bb = key[ixj];
                        bool up = ((i & k) == 0);
                        if (up ? (a < bb) : (a > bb)) { key[i] = bb; key[ixj] = a; }
                    }
                }
                __syncthreads();
            }
        }

        // emit top K
        for (int k = tid; k < Kn; k += blockDim.x) {
            unsigned long long v = key[k];
            int d = b*Kn + k;
            if ((v >> 32) != 0ULL) {     // real candidate (score > 0.05 > 0)
                int slot = (int)(v & 0x7FFFu);
                int o = b*CAP + slot;
                float s   = g_cand_score[o];
                int flat  = g_cand_flat[o];
                int lab   = flat / Nn + 1;
                float4 bx = g_cand_box[o];
                out[OFF_B + d*4 + 0] = bx.x;
                out[OFF_B + d*4 + 1] = bx.y;
                out[OFF_B + d*4 + 2] = bx.z;
                out[OFF_B + d*4 + 3] = bx.w;
                out[OFF_S + d] = s;
                out[OFF_L + d] = (float)lab;
                g_labels[d] = lab;
            } else {
                out[OFF_B + d*4 + 0] = 0.0f;
                out[OFF_B + d*4 + 1] = 0.0f;
                out[OFF_B + d*4 + 2] = 0.0f;
                out[OFF_B + d*4 + 3] = 0.0f;
                out[OFF_S + d] = 0.0f;
                out[OFF_L + d] = 0.0f;
                g_labels[d] = 0;
            }
        }
        return;
    }

    // ---------- fallback: V > SORT_N (destructive argmax, original path) ----------
    for (int j = tid; j < V; j += blockDim.x) {
        int o = b*CAP + j;
        g_key[o] = ((unsigned long long)__float_as_uint(g_cand_score[o]) << 32)
                 | (unsigned long long)(0xFFFFFFFFu - (unsigned)g_cand_flat[o]);
    }
    __syncthreads();

    __shared__ unsigned long long sk[512];
    __shared__ int si[512];

    for (int k = 0; k < Kn; ++k) {
        unsigned long long bk = 0ULL; int bj = -1;
        for (int j = tid; j < V; j += blockDim.x) {
            unsigned long long v = g_key[b*CAP + j];
            if (v > bk) { bk = v; bj = j; }
        }
        sk[tid] = bk; si[tid] = bj;
        __syncthreads();
        for (int s = 256; s > 0; s >>= 1) {
            if (tid < s && sk[tid+s] > sk[tid]) { sk[tid] = sk[tid+s]; si[tid] = si[tid+s]; }
            __syncthreads();
        }
        if (tid == 0) {
            int d = b*Kn + k;
            if (sk[0] > 0ULL) {
                int o = b*CAP + si[0];
                float s  = g_cand_score[o];
                int flat = g_cand_flat[o];
                int lab  = flat / Nn + 1;
                float4 bx = g_cand_box[o];
                out[OFF_B + d*4 + 0] = bx.x;
                out[OFF_B + d*4 + 1] = bx.y;
                out[OFF_B + d*4 + 2] = bx.z;
                out[OFF_B + d*4 + 3] = bx.w;
                out[OFF_S + d] = s;
                out[OFF_L + d] = (float)lab;
                g_labels[d] = lab;
                g_key[o] = 0ULL;
            } else {
                out[OFF_B + d*4 + 0] = 0.0f;
                out[OFF_B + d*4 + 1] = 0.0f;
                out[OFF_B + d*4 + 2] = 0.0f;
                out[OFF_B + d*4 + 3] = 0.0f;
                out[OFF_S + d] = 0.0f;
                out[OFF_L + d] = 0.0f;
                g_labels[d] = 0;
            }
        }
        __syncthreads();
    }
}

// ---------------- kernel 4: mask gather + sigmoid ----------------
// grid = B*K, block = 256
__global__ void k_mask(const float* __restrict__ ml, float* __restrict__ out) {
    int d = blockIdx.x;                // b*K + k
    int lab = g_labels[d];
    const float* src = ml + ((size_t)d*Cn + lab)*MM;
    float* dst = out + OFF_M + (size_t)d*MM;
    for (int t = threadIdx.x; t < MM; t += blockDim.x) {
        float x = src[t];
        float p = (x >= 0.0f) ? 1.0f/(1.0f + expf(-x))
                              : expf(x)/(1.0f + expf(x));
        dst[t] = p;
    }
}

extern "C" void kernel_launch(void* const* d_in, const int* in_sizes, int n_in,
                              void* d_out, int out_size) {
    const float* logits = (const float*)d_in[0];   // [B*N, C]
    const float* reg    = (const float*)d_in[1];   // [B*N, C*4]
    const float* props  = (const float*)d_in[2];   // [B, N, 4]
    const float* ml     = (const float*)d_in[3];   // [B, K, C, M, M]
    float* out = (float*)d_out;

    k_init<<<1, 32>>>();
    k_softmax_decode<<<Bn*Nn, 128>>>(logits, reg, props);
    k_nms<<<Bn*(Cn-1), 256>>>();
    k_topk<<<Bn, 512>>>(out);
    k_mask<<<Bn*Kn, 256>>>(ml, out);
}

// round 3
// speedup vs baseline: 2.1846x; 1.4053x over previous
#include <cuda_runtime.h>
#include <math.h>

// Problem constants (match reference)
#define Bn 8
#define Nn 1000
#define Cn 81
#define CR (Cn-1)
#define Kn 100
#define Mn 28
#define MM (Mn*Mn)
#define IMG_W 1216.0f
#define IMG_H 800.0f
#define SCORE_THRESH 0.05f
#define NMS_THRESH 0.5f
#define BBOX_CLIP 4.135166556742356f   // log(1000/16)
#define SLOT 1024                       // per-class survivor capacity (>= Nn worst case? m<=1000<=1024 ok)
#define TSEL 2048                       // top-k selection smem cap

// Output layout: concat of [B,K,4] boxes, [B,K] scores, [B,K] labels, [B,K,1,M,M] masks (all f32)
#define OFF_B 0
#define OFF_S (Bn*Kn*4)
#define OFF_L (OFF_S + Bn*Kn)
#define OFF_M (OFF_L + Bn*Kn)

// ---------------- scratch (device globals; no allocation) ----------------
__device__ float g_scores[Bn*CR*Nn];           // [b][cr][n], classes 1..80 only
__device__ int   g_cls_count[Bn*CR];           // survivors per (b,class)
__device__ float g_cand_score[Bn*CR*SLOT];
__device__ int   g_cand_flat [Bn*CR*SLOT];
__device__ float4 g_cand_box [Bn*CR*SLOT];
__device__ int   g_labels[Bn*Kn];
__device__ unsigned long long g_fb_key[Bn*CR*SLOT];  // exact fallback only

// ---------------- kernel 1: softmax only ----------------
// grid = B*N rows, block = 128 (thread c handles class c)
__global__ void k_softmax(const float* __restrict__ logits) {
    int row = blockIdx.x;            // b*N + n
    int c = threadIdx.x;
    int lane = c & 31;
    int wid = c >> 5;
    __shared__ float redm[4];
    __shared__ float reds[4];

    float v = (c < Cn) ? logits[row*Cn + c] : -INFINITY;
    float wm = v;
    #pragma unroll
    for (int off = 16; off > 0; off >>= 1)
        wm = fmaxf(wm, __shfl_xor_sync(0xFFFFFFFFu, wm, off));
    if (lane == 0) redm[wid] = wm;
    __syncthreads();
    float mx = fmaxf(fmaxf(redm[0], redm[1]), fmaxf(redm[2], redm[3]));

    float e = (c < Cn) ? expf(v - mx) : 0.0f;
    float ws = e;
    #pragma unroll
    for (int off = 16; off > 0; off >>= 1)
        ws += __shfl_xor_sync(0xFFFFFFFFu, ws, off);
    if (lane == 0) reds[wid] = ws;
    __syncthreads();
    float sum = reds[0] + reds[1] + reds[2] + reds[3];

    if (c >= 1 && c < Cn) {
        int b = row / Nn;
        int n = row % Nn;
        g_scores[((size_t)(b*CR) + (c-1))*Nn + n] = e / sum;
    }
}

// ---------------- kernel 2: filter -> sort -> decode -> NMS per (b,class) ----
// grid = B*CR, block = 128
__global__ void k_nms(const float* __restrict__ reg,
                      const float* __restrict__ props) {
    int pair = blockIdx.x;
    int b  = pair / CR;
    int cr = pair % CR;
    int cc = cr + 1;
    int tid = threadIdx.x;

    __shared__ unsigned long long key[SLOT];
    __shared__ float4 box[SLOT];
    __shared__ float  area[SLOT];
    __shared__ unsigned char keep[SLOT];
    __shared__ int cntS, scntS;

    if (tid == 0) { cntS = 0; scntS = 0; }
    __syncthreads();

    // compact above-threshold candidates (order arbitrary; sort restores determinism)
    const float* sc = g_scores + ((size_t)(b*CR) + cr)*Nn;
    for (int i = tid; i < Nn; i += blockDim.x) {
        float s = sc[i];
        if (s > SCORE_THRESH) {
            int p = atomicAdd(&cntS, 1);
            key[p] = ((unsigned long long)__float_as_uint(s) << 32)
                   | (unsigned long long)(0xFFFFFFFFu - (unsigned)i);
        }
    }
    __syncthreads();
    int m = cntS;

    if (m > 0) {
        // pad to next pow2
        int sn = 1; while (sn < m) sn <<= 1; if (sn < 2) sn = 2;
        for (int i = m + tid; i < sn; i += blockDim.x) key[i] = 0ULL;
        __syncthreads();

        // bitonic sort DESCENDING over sn keys
        for (int k = 2; k <= sn; k <<= 1) {
            for (int j = k >> 1; j > 0; j >>= 1) {
                for (int i = tid; i < sn; i += blockDim.x) {
                    int ixj = i ^ j;
                    if (ixj > i) {
                        unsigned long long a = key[i], bb = key[ixj];
                        bool up = ((i & k) == 0);
                        if (up ? (a < bb) : (a > bb)) { key[i] = bb; key[ixj] = a; }
                    }
                }
                __syncthreads();
            }
        }

        // decode + clip boxes for the m sorted candidates
        for (int i = tid; i < m; i += blockDim.x) {
            unsigned orig = 0xFFFFFFFFu - (unsigned)(key[i] & 0xFFFFFFFFull);
            int row = b*Nn + (int)orig;
            float px1 = props[row*4+0], py1 = props[row*4+1];
            float px2 = props[row*4+2], py2 = props[row*4+3];
            float w = px2 - px1, h = py2 - py1;
            float cx = px1 + 0.5f*w, cy = py1 + 0.5f*h;
            const float* r = reg + (size_t)row*Cn*4 + cc*4;
            float dx = r[0] / 10.0f;
            float dy = r[1] / 10.0f;
            float dw = fminf(r[2] / 5.0f, BBOX_CLIP);
            float dh = fminf(r[3] / 5.0f, BBOX_CLIP);
            float pcx = dx*w + cx;
            float pcy = dy*h + cy;
            float pw = expf(dw)*w;
            float ph = expf(dh)*h;
            float x1 = pcx - 0.5f*pw, y1 = pcy - 0.5f*ph;
            float x2 = pcx + 0.5f*pw, y2 = pcy + 0.5f*ph;
            x1 = fminf(fmaxf(x1, 0.0f), IMG_W);
            y1 = fminf(fmaxf(y1, 0.0f), IMG_H);
            x2 = fminf(fmaxf(x2, 0.0f), IMG_W);
            y2 = fminf(fmaxf(y2, 0.0f), IMG_H);
            float4 bv; bv.x = x1; bv.y = y1; bv.z = x2; bv.w = y2;
            box[i] = bv;
            area[i] = (x2 - x1) * (y2 - y1);
            keep[i] = 1;
        }
        __syncthreads();

        // sequential greedy suppression
        for (int i = 0; i < m; ++i) {
            __syncthreads();
            if (!keep[i]) continue;            // uniform after barrier
            float4 bi = box[i];
            float ai = area[i];
            for (int j = i + 1 + tid; j < m; j += blockDim.x) {
                float4 bj = box[j];
                float lx = fmaxf(bi.x, bj.x);
                float ly = fmaxf(bi.y, bj.y);
                float rx = fminf(bi.z, bj.z);
                float ry = fminf(bi.w, bj.w);
                float iw = fmaxf(rx - lx, 0.0f);
                float ih = fmaxf(ry - ly, 0.0f);
                float inter = iw * ih;
                float iou = inter / (ai + area[j] - inter + 1e-9f);
                if (iou > NMS_THRESH) keep[j] = 0;
            }
        }
        __syncthreads();

        // write survivors (any order; each record self-contained)
        for (int i = tid; i < m; i += blockDim.x) {
            if (keep[i]) {
                int j = atomicAdd(&scntS, 1);
                int o = (b*CR + cr)*SLOT + j;
                g_cand_score[o] = __uint_as_float((unsigned)(key[i] >> 32));
                g_cand_flat[o]  = cr*Nn + i;
                g_cand_box[o]   = box[i];
            }
        }
        __syncthreads();
    }
    if (tid == 0) g_cls_count[b*CR + cr] = scntS;
}

// ---------------- kernel 3: per-image top-K via radix-select + small sort ----
// grid = B, block = 512
__global__ void k_topk(float* __restrict__ out) {
    int b = blockIdx.x;
    int tid = threadIdx.x;

    __shared__ int hist[4096];       // 12-bit score-bit bins
    __shared__ int ssum[512];
    __shared__ int ccounts[CR];
    __shared__ unsigned long long skey[TSEL];
    __shared__ int spay[TSEL];
    __shared__ int p_sh, nsel_sh, total_sh, cc_sh;

    if (tid < CR) ccounts[tid] = g_cls_count[b*CR + tid];
    for (int i = tid; i < 4096; i += 512) hist[i] = 0;
    if (tid == 0) { p_sh = 0; cc_sh = 0; }
    __syncthreads();

    // pass 1: histogram top-12 score bits
    for (int cr = 0; cr < CR; ++cr) {
        int cnt = ccounts[cr];
        for (int j = tid; j < cnt; j += 512) {
            unsigned bits = __float_as_uint(g_cand_score[(b*CR + cr)*SLOT + j]);
            atomicAdd(&hist[bits >> 20], 1);
        }
    }
    __syncthreads();

    // suffix scan: per-thread chunk of 8 bins, reversed Hillis-Steele
    int csum = 0;
    #pragma unroll
    for (int q = 0; q < 8; ++q) csum += hist[tid*8 + q];
    ssum[511 - tid] = csum;
    __syncthreads();
    for (int off = 1; off < 512; off <<= 1) {
        int v = ssum[tid];
        int add = (tid >= off) ? ssum[tid - off] : 0;
        __syncthreads();
        ssum[tid] = v + add;
        __syncthreads();
    }
    int suf_incl = ssum[511 - tid];
    int suf_excl = suf_incl - csum;
    if (tid == 0) { total_sh = ssum[511]; nsel_sh = ssum[511]; }
    __syncthreads();
    // unique crossing thread finds pivot p = max bin with S(bin) >= K
    if (suf_excl < Kn && suf_incl >= Kn) {
        int running = suf_excl;
        for (int q = 7; q >= 0; --q) {
            int bin = tid*8 + q;
            running += hist[bin];
            if (running >= Kn) { p_sh = bin; nsel_sh = running; break; }
        }
    }
    __syncthreads();
    int p = p_sh;
    int nsel = nsel_sh;

    if (nsel <= TSEL) {
        // pass 2: compact selected candidates
        for (int cr = 0; cr < CR; ++cr) {
            int cnt = ccounts[cr];
            for (int j = tid; j < cnt; j += 512) {
                int o = (b*CR + cr)*SLOT + j;
                unsigned bits = __float_as_uint(g_cand_score[o]);
                if ((int)(bits >> 20) >= p) {
                    int pos = atomicAdd(&cc_sh, 1);
                    unsigned flat = (unsigned)g_cand_flat[o];
                    skey[pos] = ((unsigned long long)bits << 17)
                              | (unsigned long long)(0x1FFFFu - flat);
                    spay[pos] = cr*SLOT + j;
                }
            }
        }
        __syncthreads();

        // sort nsel pairs descending (pad to pow2)
        int sn = 1; while (sn < nsel) sn <<= 1; if (sn < 2) sn = 2;
        for (int i = nsel + tid; i < sn; i += 512) skey[i] = 0ULL;
        __syncthreads();
        for (int k = 2; k <= sn; k <<= 1) {
            for (int j = k >> 1; j > 0; j >>= 1) {
                for (int i = tid; i < sn; i += 512) {
                    int ixj = i ^ j;
                    if (ixj > i) {
                        unsigned long long a = skey[i], bb = skey[ixj];
                        bool up = ((i & k) == 0);
                        if (up ? (a < bb) : (a > bb)) {
                            skey[i] = bb; skey[ixj] = a;
                            int t2 = spay[i]; spay[i] = spay[ixj]; spay[ixj] = t2;
                        }
                    }
                }
                __syncthreads();
            }
        }

        // emit top K
        if (tid < Kn) {
            int d = b*Kn + tid;
            unsigned long long v = (tid < sn) ? skey[tid] : 0ULL;
            if (tid < nsel && v != 0ULL) {
                int o = b*CR*SLOT + spay[tid];
                float s   = g_cand_score[o];
                int flat  = g_cand_flat[o];
                int lab   = flat / Nn + 1;
                float4 bx = g_cand_box[o];
                out[OFF_B + d*4 + 0] = bx.x;
                out[OFF_B + d*4 + 1] = bx.y;
                out[OFF_B + d*4 + 2] = bx.z;
                out[OFF_B + d*4 + 3] = bx.w;
                out[OFF_S + d] = s;
                out[OFF_L + d] = (float)lab;
                g_labels[d] = lab;
            } else {
                out[OFF_B + d*4 + 0] = 0.0f;
                out[OFF_B + d*4 + 1] = 0.0f;
                out[OFF_B + d*4 + 2] = 0.0f;
                out[OFF_B + d*4 + 3] = 0.0f;
                out[OFF_S + d] = 0.0f;
                out[OFF_L + d] = 0.0f;
                g_labels[d] = 0;
            }
        }
        return;
    }

    // ---------- exact fallback (pathological tie storm): destructive argmax ----------
    for (int cr = 0; cr < CR; ++cr) {
        int cnt = ccounts[cr];
        for (int j = tid; j < SLOT; j += 512) {
            int o = (b*CR + cr)*SLOT + j;
            if (j < cnt) {
                unsigned bits = __float_as_uint(g_cand_score[o]);
                unsigned flat = (unsigned)g_cand_flat[o];
                g_fb_key[o] = ((unsigned long long)bits << 17)
                            | (unsigned long long)(0x1FFFFu - flat);
            } else g_fb_key[o] = 0ULL;
        }
    }
    __syncthreads();
    __shared__ unsigned long long rk[512];
    __shared__ int ri[512];
    for (int k = 0; k < Kn; ++k) {
        unsigned long long bk = 0ULL; int bj = -1;
        for (int j = tid; j < CR*SLOT; j += 512) {
            unsigned long long v = g_fb_key[b*CR*SLOT + j];
            if (v > bk) { bk = v; bj = j; }
        }
        rk[tid] = bk; ri[tid] = bj;
        __syncthreads();
        for (int s = 256; s > 0; s >>= 1) {
            if (tid < s && rk[tid+s] > rk[tid]) { rk[tid] = rk[tid+s]; ri[tid] = ri[tid+s]; }
            __syncthreads();
        }
        if (tid == 0) {
            int d = b*Kn + k;
            if (rk[0] != 0ULL) {
                int o = b*CR*SLOT + ri[0];
                float s  = g_cand_score[o];
                int flat = g_cand_flat[o];
                int lab  = flat / Nn + 1;
                float4 bx = g_cand_box[o];
                out[OFF_B + d*4 + 0] = bx.x;
                out[OFF_B + d*4 + 1] = bx.y;
                out[OFF_B + d*4 + 2] = bx.z;
                out[OFF_B + d*4 + 3] = bx.w;
                out[OFF_S + d] = s;
                out[OFF_L + d] = (float)lab;
                g_labels[d] = lab;
                g_fb_key[o] = 0ULL;
            } else {
                out[OFF_B + d*4 + 0] = 0.0f;
                out[OFF_B + d*4 + 1] = 0.0f;
                out[OFF_B + d*4 + 2] = 0.0f;
                out[OFF_B + d*4 + 3] = 0.0f;
                out[OFF_S + d] = 0.0f;
                out[OFF_L + d] = 0.0f;
                g_labels[d] = 0;
            }
        }
        __syncthreads();
    }
}

// ---------------- kernel 4: mask gather + sigmoid ----------------
// grid = B*K, block = 256
__global__ void k_mask(const float* __restrict__ ml, float* __restrict__ out) {
    int d = blockIdx.x;                // b*K + k
    int lab = g_labels[d];
    const float* src = ml + ((size_t)d*Cn + lab)*MM;
    float* dst = out + OFF_M + (size_t)d*MM;
    for (int t = threadIdx.x; t < MM; t += blockDim.x) {
        float x = src[t];
        float p = (x >= 0.0f) ? 1.0f/(1.0f + expf(-x))
                              : expf(x)/(1.0f + expf(x));
        dst[t] = p;
    }
}

extern "C" void kernel_launch(void* const* d_in, const int* in_sizes, int n_in,
                              void* d_out, int out_size) {
    const float* logits = (const float*)d_in[0];   // [B*N, C]
    const float* reg    = (const float*)d_in[1];   // [B*N, C*4]
    const float* props  = (const float*)d_in[2];   // [B, N, 4]
    const float* ml     = (const float*)d_in[3];   // [B, K, C, M, M]
    float* out = (float*)d_out;

    k_softmax<<<Bn*Nn, 128>>>(logits);
    k_nms<<<Bn*CR, 128>>>(reg, props);
    k_topk<<<Bn, 512>>>(out);
    k_mask<<<Bn*Kn, 256>>>(ml, out);
}